// round 1
// baseline (speedup 1.0000x reference)
#include <cuda_runtime.h>

// MWPT: 3-level wavelet packet transform, fused into one kernel.
// x: [128,1,65536] f32, kernel: [1,1,8] f32.
// out = concat(level1 [128,2,32768], level2 [128,4,16384], level3 [128,8,8192])
// level2 node order [b0,b2,b6,b4]; level3 order [c0,c1,c3,c2,c6,c7,c5,c4].
//
// conv: out[n] = sum_k x[(2n + k - 3) mod L] * w[k]  (circular, stride 2)
// hi-pass QMF: w_hi[k] = (-1)^k * w_lo[7-k]
//
// Wrap commutes through the chain (2*L_next = L_prev), so wrap only at x load.

namespace {
constexpr int T       = 65536;
constexpr int KS      = 8;
constexpr int N3      = 1024;            // level-3 outputs per node per block
constexpr int N2      = 2 * N3 + 6;      // 2054 level-2 samples needed per node
constexpr int N1      = 2 * N2 + 6;      // 4114 level-1 samples needed per node
constexpr int NX      = 2 * N1 + 6;      // 8234 x samples needed
constexpr int THREADS = 256;
constexpr int SMEM_FLOATS = NX + 2 * N1 + 4 * N2;   // 24678
constexpr int SMEM_BYTES  = SMEM_FLOATS * (int)sizeof(float);

constexpr long OUT1_BASE = 0;
constexpr long OUT2_BASE = 128L * 2 * 32768;         // 8388608
constexpr long OUT3_BASE = OUT2_BASE + 128L * 4 * 16384; // 16777216
}

__global__ __launch_bounds__(THREADS) void mwpt_kernel(
    const float* __restrict__ x,
    const float* __restrict__ kern,
    float* __restrict__ out)
{
    extern __shared__ float sm[];
    float* sx = sm;            // [NX]
    float* s1 = sx + NX;       // [2][N1]  (node 0 = low a0, node 1 = high a4)
    float* s2 = s1 + 2 * N1;   // [4][N2]  (b0, b2, b4, b6)

    const int b  = blockIdx.y;        // batch row
    const int n0 = blockIdx.x * N3;   // first owned level-3 output index

    // Filters in registers (8 floats each; L1-cached LDG)
    float wlo[KS], whi[KS];
    #pragma unroll
    for (int k = 0; k < KS; ++k) wlo[k] = __ldg(&kern[k]);
    #pragma unroll
    for (int k = 0; k < KS; ++k) whi[k] = (k & 1) ? -wlo[KS - 1 - k] : wlo[KS - 1 - k];

    // ---- Load x slice with circular wrap ----
    // Chain of halos: level3 local n needs level2 idx 2n+k (k<8);
    // global bases: m0 = 2n0-3, l0 = 4n0-9, j0 = 8n0-21.
    const float* xb = x + (size_t)b * T;
    const int j0 = 8 * n0 - 21;
    for (int i = threadIdx.x; i < NX; i += THREADS)
        sx[i] = xb[(j0 + i) & (T - 1)];   // & works for negative ints (2's comp)
    __syncthreads();

    // ---- Level 1: both QMF branches per smem read ----
    for (int i = threadIdx.x; i < N1; i += THREADS) {
        float lo = 0.f, hi = 0.f;
        #pragma unroll
        for (int k = 0; k < KS; ++k) {
            float v = sx[2 * i + k];
            lo += v * wlo[k];
            hi += v * whi[k];
        }
        s1[i]      = lo;
        s1[N1 + i] = hi;
    }
    __syncthreads();

    // ---- Write level-1 owned slice: global [4n0, 4n0+4N3), local offset 9 ----
    {
        float* o1 = out + OUT1_BASE + (size_t)b * (2 * 32768);
        const int g0 = 4 * n0;
        for (int i = threadIdx.x; i < 4 * N3; i += THREADS) {
            o1[g0 + i]         = s1[9 + i];        // a0 -> node 0
            o1[32768 + g0 + i] = s1[N1 + 9 + i];   // a4 -> node 1
        }
    }

    // ---- Level 2: 4 nodes from 2 parents ----
    for (int i = threadIdx.x; i < N2; i += THREADS) {
        float r0 = 0.f, r1 = 0.f, r2 = 0.f, r3 = 0.f;
        #pragma unroll
        for (int k = 0; k < KS; ++k) {
            float v0 = s1[2 * i + k];
            float v1 = s1[N1 + 2 * i + k];
            r0 += v0 * wlo[k];  r1 += v0 * whi[k];   // b0, b2
            r2 += v1 * wlo[k];  r3 += v1 * whi[k];   // b4, b6
        }
        s2[i]          = r0;
        s2[N2 + i]     = r1;
        s2[2 * N2 + i] = r2;
        s2[3 * N2 + i] = r3;
    }
    __syncthreads();

    // ---- Write level-2 owned slice: global [2n0, 2n0+2N3), local offset 3 ----
    // Output node order [b0, b2, b6, b4] => s2 idx {0,1,2,3} -> pos {0,1,3,2}
    {
        float* o2 = out + OUT2_BASE + (size_t)b * (4 * 16384);
        const int g0 = 2 * n0;
        for (int i = threadIdx.x; i < 2 * N3; i += THREADS) {
            o2[0 * 16384 + g0 + i] = s2[0 * N2 + 3 + i];   // b0 -> pos 0
            o2[1 * 16384 + g0 + i] = s2[1 * N2 + 3 + i];   // b2 -> pos 1
            o2[3 * 16384 + g0 + i] = s2[2 * N2 + 3 + i];   // b4 -> pos 3
            o2[2 * 16384 + g0 + i] = s2[3 * N2 + 3 + i];   // b6 -> pos 2
        }
    }

    // ---- Level 3: compute and stream straight to GMEM ----
    // c_{2p} = lo(parent p), c_{2p+1} = hi(parent p)
    // Output order [c0,c1,c3,c2,c6,c7,c5,c4] => c_j positions {0,1,3,2,7,6,4,5}
    {
        float* o3 = out + OUT3_BASE + (size_t)b * (8 * 8192);
        for (int i = threadIdx.x; i < N3; i += THREADS) {
            const int g = n0 + i;
            #pragma unroll
            for (int p = 0; p < 4; ++p) {
                float lo = 0.f, hi = 0.f;
                #pragma unroll
                for (int k = 0; k < KS; ++k) {
                    float v = s2[p * N2 + 2 * i + k];
                    lo += v * wlo[k];
                    hi += v * whi[k];
                }
                const int pos_lo = (p == 0) ? 0 : (p == 1) ? 3 : (p == 2) ? 7 : 4;
                const int pos_hi = (p == 0) ? 1 : (p == 1) ? 2 : (p == 2) ? 6 : 5;
                o3[pos_lo * 8192 + g] = lo;
                o3[pos_hi * 8192 + g] = hi;
            }
        }
    }
}

extern "C" void kernel_launch(void* const* d_in, const int* in_sizes, int n_in,
                              void* d_out, int out_size)
{
    const float* x    = (const float*)d_in[0];
    const float* kern = (const float*)d_in[1];
    float* out        = (float*)d_out;

    // >48KB dynamic smem requires explicit opt-in (idempotent, capture-safe).
    cudaFuncSetAttribute(mwpt_kernel,
                         cudaFuncAttributeMaxDynamicSharedMemorySize,
                         SMEM_BYTES);

    dim3 grid(8192 / N3, 128);   // (8 chunks, 128 batch rows)
    mwpt_kernel<<<grid, THREADS, SMEM_BYTES>>>(x, kern, out);
}